// round 6
// baseline (speedup 1.0000x reference)
#include <cuda_runtime.h>
#include <cuda_bf16.h>
#include <math.h>
#include <stdint.h>

// Problem constants
#define B_ 2
#define T_ 2048
#define C_ 1024
#define H_ 16
#define D_ 64
#define WIN_ 512
#define K_ 1024

// GEMM tiling
#define BK 32
#define SP 40                       // padded smem row stride (bf16 elems)
#define TILE_B (128 * SP * 2)       // bytes per 128xBK tile (10240)
#define STAGE_B (4 * TILE_B)        // 4 tiles (Ah, Al, Wh, Wl) = 40960
#define GSMEM (2 * STAGE_B)         // 2 stages = 81920

// Attention smem
#define ASP 72                      // padded row stride (bf16 elems)
#define ATTN_SMEM ((2*128 + 4*64) * ASP * 2)   // 73728 bytes

// ---------------- scratch (allocation-free) ----------------
__device__ __nv_bfloat16 g_Qh[B_*H_*T_*D_], g_Ql[B_*H_*T_*D_];
__device__ __nv_bfloat16 g_Kh[B_*H_*T_*D_], g_Kl[B_*H_*T_*D_];
__device__ __nv_bfloat16 g_Vh[B_*H_*T_*D_], g_Vl[B_*H_*T_*D_];
__device__ __nv_bfloat16 g_xh[B_*T_*C_],  g_xl[B_*T_*C_];
__device__ __nv_bfloat16 g_wqh[3*C_*C_],  g_wql[3*C_*C_];
__device__ __nv_bfloat16 g_wph[C_*C_],    g_wpl[C_*C_];
__device__ __nv_bfloat16 g_ah[B_*T_*C_],  g_al[B_*T_*C_];

__device__ __forceinline__ uint32_t smem_u32(const void* p) {
    uint32_t a;
    asm("{ .reg .u64 t; cvta.to.shared.u64 t, %1; cvt.u32.u64 %0, t; }"
        : "=r"(a) : "l"(p));
    return a;
}
#define LDMX4(r0, r1, r2, r3, addr)                                          \
    asm volatile("ldmatrix.sync.aligned.m8n8.x4.shared.b16 {%0,%1,%2,%3}, [%4];" \
        : "=r"(r0), "=r"(r1), "=r"(r2), "=r"(r3) : "r"(addr))
#define LDMX4T(r0, r1, r2, r3, addr)                                         \
    asm volatile("ldmatrix.sync.aligned.m8n8.x4.trans.shared.b16 {%0,%1,%2,%3}, [%4];" \
        : "=r"(r0), "=r"(r1), "=r"(r2), "=r"(r3) : "r"(addr))
#define MMA16816(c, a0, a1, a2, a3, b0, b1)                                  \
    asm volatile("mma.sync.aligned.m16n8k16.row.col.f32.bf16.bf16.f32 "      \
        "{%0,%1,%2,%3}, {%4,%5,%6,%7}, {%8,%9}, {%0,%1,%2,%3};"              \
        : "+f"((c)[0]), "+f"((c)[1]), "+f"((c)[2]), "+f"((c)[3])             \
        : "r"(a0), "r"(a1), "r"(a2), "r"(a3), "r"(b0), "r"(b1))
#define PACKBF2(r, lo, hi)                                                   \
    asm("cvt.rn.bf16x2.f32 %0, %1, %2;" : "=r"(r) : "f"(hi), "f"(lo))
#define CP16(dst, src)                                                       \
    asm volatile("cp.async.cg.shared.global [%0], [%1], 16;" :: "r"(dst), "l"(src))
#define CP_COMMIT() asm volatile("cp.async.commit_group;" ::: "memory")
#define CP_WAIT(n)  asm volatile("cp.async.wait_group %0;" :: "n"(n) : "memory")

// ---------------- split fp32 -> bf16 hi/lo ----------------
__global__ __launch_bounds__(256) void split_kernel(
    const float* __restrict__ s, __nv_bfloat16* __restrict__ hi,
    __nv_bfloat16* __restrict__ lo, int n4)
{
    int i = blockIdx.x * 256 + threadIdx.x;
    if (i >= n4) return;
    float4 v = ((const float4*)s)[i];
    __nv_bfloat16 h0 = __float2bfloat16(v.x), h1 = __float2bfloat16(v.y);
    __nv_bfloat16 h2 = __float2bfloat16(v.z), h3 = __float2bfloat16(v.w);
    __nv_bfloat16 l0 = __float2bfloat16(v.x - __bfloat162float(h0));
    __nv_bfloat16 l1 = __float2bfloat16(v.y - __bfloat162float(h1));
    __nv_bfloat16 l2 = __float2bfloat16(v.z - __bfloat162float(h2));
    __nv_bfloat16 l3 = __float2bfloat16(v.w - __bfloat162float(h3));
    ((__nv_bfloat162*)hi)[2*i]   = __nv_bfloat162(h0, h1);
    ((__nv_bfloat162*)hi)[2*i+1] = __nv_bfloat162(h2, h3);
    ((__nv_bfloat162*)lo)[2*i]   = __nv_bfloat162(l0, l1);
    ((__nv_bfloat162*)lo)[2*i+1] = __nv_bfloat162(l2, l3);
}

// ---------------- bf16-split tensor-core GEMM (HMMA + cp.async) --------
// D[m,n] = sum_k A[m,k]*W[n,k] + bias[n] ~= Ah*Wh + Ah*Wl + Al*Wh.
// CTA 128x128, BK=32, 256 threads = 8 warps (4m x 2n), warp tile 32x64.
// 2-stage cp.async pipeline. 2 CTAs/SM.
// MODE 0: split-scatter into g_{Q,K,V}{h,l}.  MODE 1: fp32 row-major out.
template <int MODE>
__global__ __launch_bounds__(256, 2) void gemm_bf16_kernel(
    const __nv_bfloat16* __restrict__ Ahi, const __nv_bfloat16* __restrict__ Alo,
    const __nv_bfloat16* __restrict__ Bhi, const __nv_bfloat16* __restrict__ Blo,
    const float* __restrict__ bias, float* __restrict__ Cout)
{
    extern __shared__ char smem[];
    const uint32_t sb = smem_u32(smem);
    const int tid = threadIdx.x;
    const int wid = tid >> 5;
    const int lane = tid & 31;
    const int warp_m = wid & 3;      // 0..3, 32 rows each
    const int warp_n = wid >> 2;     // 0..1, 64 cols each
    const int bn = blockIdx.x, bm = blockIdx.y;

    // cp.async mapping: per tile, thread -> row (tid>>1), 32B chunk ((tid&1)*16 bf16)
    const int grow = tid >> 1;
    const int gc16 = (tid & 1) * 16;
    const __nv_bfloat16* srcs[4] = {
        Ahi + (size_t)(bm * 128 + grow) * K_ + gc16,
        Alo + (size_t)(bm * 128 + grow) * K_ + gc16,
        Bhi + (size_t)(bn * 128 + grow) * K_ + gc16,
        Blo + (size_t)(bn * 128 + grow) * K_ + gc16 };
    const uint32_t soff = (uint32_t)(grow * SP + gc16) * 2;

    // ldmatrix per-lane offsets (bytes within a tile)
    const uint32_t aoff = (uint32_t)(
        (warp_m * 32 + (lane & 7) + ((lane >> 3) & 1) * 8) * SP
        + (lane >> 4) * 8) * 2;
    const uint32_t boff = (uint32_t)(
        (warp_n * 64 + (lane & 7) + (lane >> 4) * 8) * SP
        + ((lane >> 3) & 1) * 8) * 2;

    float acc[2][8][4];
    #pragma unroll
    for (int i = 0; i < 2; i++)
        #pragma unroll
        for (int j = 0; j < 8; j++)
            #pragma unroll
            for (int c = 0; c < 4; c++) acc[i][j][c] = 0.f;

    const int NT = K_ / BK;   // 32

    // prologue: stages 0 and 1
    #pragma unroll
    for (int st = 0; st < 2; st++) {
        const uint32_t db = sb + st * STAGE_B;
        #pragma unroll
        for (int t = 0; t < 4; t++) {
            CP16(db + t * TILE_B + soff,      srcs[t] + st * BK);
            CP16(db + t * TILE_B + soff + 16, srcs[t] + st * BK + 8);
        }
        CP_COMMIT();
    }

    for (int it = 0; it < NT; ++it) {
        if (it == NT - 1) { CP_WAIT(0); } else { CP_WAIT(1); }
        __syncthreads();
        const uint32_t tb = sb + (uint32_t)(it & 1) * STAGE_B;

        #pragma unroll
        for (int kk = 0; kk < BK; kk += 16) {
            uint32_t ah[2][4], al[2][4];
            #pragma unroll
            for (int mf = 0; mf < 2; mf++) {
                const uint32_t ao = tb + aoff + (uint32_t)(mf * 16 * SP + kk) * 2;
                LDMX4(ah[mf][0], ah[mf][1], ah[mf][2], ah[mf][3], ao);
                LDMX4(al[mf][0], al[mf][1], al[mf][2], al[mf][3], ao + TILE_B);
            }
            #pragma unroll
            for (int nf2 = 0; nf2 < 4; nf2++) {
                uint32_t bh[4], bl[4];
                const uint32_t bo = tb + 2 * TILE_B + boff
                                  + (uint32_t)(nf2 * 16 * SP + kk) * 2;
                LDMX4(bh[0], bh[1], bh[2], bh[3], bo);
                LDMX4(bl[0], bl[1], bl[2], bl[3], bo + TILE_B);
                #pragma unroll
                for (int mf = 0; mf < 2; mf++) {
                    MMA16816(acc[mf][nf2*2], ah[mf][0], ah[mf][1], ah[mf][2], ah[mf][3],
                             bh[0], bh[1]);
                    MMA16816(acc[mf][nf2*2], ah[mf][0], ah[mf][1], ah[mf][2], ah[mf][3],
                             bl[0], bl[1]);
                    MMA16816(acc[mf][nf2*2], al[mf][0], al[mf][1], al[mf][2], al[mf][3],
                             bh[0], bh[1]);
                    MMA16816(acc[mf][nf2*2+1], ah[mf][0], ah[mf][1], ah[mf][2], ah[mf][3],
                             bh[2], bh[3]);
                    MMA16816(acc[mf][nf2*2+1], ah[mf][0], ah[mf][1], ah[mf][2], ah[mf][3],
                             bl[2], bl[3]);
                    MMA16816(acc[mf][nf2*2+1], al[mf][0], al[mf][1], al[mf][2], al[mf][3],
                             bh[2], bh[3]);
                }
            }
        }
        __syncthreads();   // all warps done reading this buf before refill
        if (it + 2 < NT) {
            const uint32_t db = tb;   // reuse current buf for stage it+2
            #pragma unroll
            for (int t = 0; t < 4; t++) {
                CP16(db + t * TILE_B + soff,      srcs[t] + (it + 2) * BK);
                CP16(db + t * TILE_B + soff + 16, srcs[t] + (it + 2) * BK + 8);
            }
        }
        CP_COMMIT();   // always commit (possibly empty group)
    }
    __syncthreads();

    // stage through smem: Ep[128][129]
    float* Ep = (float*)smem;
    const int g = lane >> 2, tg = lane & 3;
    #pragma unroll
    for (int mf = 0; mf < 2; mf++)
        #pragma unroll
        for (int nf = 0; nf < 8; nf++) {
            const int r0 = warp_m * 32 + mf * 16 + g;
            const int c0 = warp_n * 64 + nf * 8 + tg * 2;
            Ep[r0 * 129 + c0]           = acc[mf][nf][0];
            Ep[r0 * 129 + c0 + 1]       = acc[mf][nf][1];
            Ep[(r0 + 8) * 129 + c0]     = acc[mf][nf][2];
            Ep[(r0 + 8) * 129 + c0 + 1] = acc[mf][nf][3];
        }
    __syncthreads();

    const int col = tid & 127;
    const int rg = tid >> 7;         // 0..1, 64 rows each
    const float biasv = bias[bn * 128 + col];
    if (MODE == 0) {
        const int sel = bn >> 3;
        const int h = ((bn & 7) << 1) + (col >> 6);
        const int dd = col & 63;
        __nv_bfloat16 *dh, *dl;
        if (sel == 0)      { dh = g_Qh; dl = g_Ql; }
        else if (sel == 1) { dh = g_Kh; dl = g_Kl; }
        else               { dh = g_Vh; dl = g_Vl; }
        #pragma unroll 4
        for (int r = 0; r < 64; r++) {
            const int row = rg * 64 + r;
            const int m = bm * 128 + row;
            const int b = m >> 11, t = m & 2047;
            const float v = Ep[row * 129 + col] + biasv;
            const __nv_bfloat16 hb = __float2bfloat16(v);
            const size_t o = (((size_t)(b * H_ + h)) * T_ + t) * D_ + dd;
            dh[o] = hb;
            dl[o] = __float2bfloat16(v - __bfloat162float(hb));
        }
    } else {
        #pragma unroll 4
        for (int r = 0; r < 64; r++) {
            const int row = rg * 64 + r;
            const int m = bm * 128 + row;
            Cout[(size_t)m * C_ + bn * 128 + col] = Ep[row * 129 + col] + biasv;
        }
    }
}

// softcap+mask+exp with fixed max 30: p = exp(-60/(E+1)), E = exp(s/15)
__device__ __forceinline__ float softp(float raw, int qr, int kg, int P) {
    const float sc = raw * 0.125f;
    const float E = __expf(sc * (1.0f / 15.0f));
    const float p = __expf(__fdividef(-60.0f, E + 1.0f));
    const bool valid = ((kg <= qr) && (qr - kg <= WIN_)) || (kg < P);
    return valid ? p : 0.0f;
}

// ---------------------------------------------------------------------------
// HMMA attention: 128 q-rows/CTA, 8 warps (16 q-rows each), 64-key tiles.
// QK^T: Qh*Kh + Qh*Kl + Ql*Kh.  PV: Ph*Vh + Ph*Vl + Pl*Vh.
// P repacked C->A fragments in registers (no smem round trip).
// ---------------------------------------------------------------------------
__global__ __launch_bounds__(256, 2) void attn_kernel(const int* __restrict__ spl)
{
    extern __shared__ __nv_bfloat16 asmem[];
    __nv_bfloat16* Qh = asmem;               // [128][ASP]
    __nv_bfloat16* Ql = Qh + 128 * ASP;
    __nv_bfloat16* Kh = Ql + 128 * ASP;      // [64][ASP]
    __nv_bfloat16* Kl = Kh + 64 * ASP;
    __nv_bfloat16* Vh = Kl + 64 * ASP;       // [64][ASP]
    __nv_bfloat16* Vl = Vh + 64 * ASP;

    const int tid = threadIdx.x;
    const int wid = tid >> 5;      // 0..7
    const int lane = tid & 31;
    const int q0 = blockIdx.x * 128;
    const int h = blockIdx.y;
    const int b = blockIdx.z;
    const size_t bh = (size_t)(b * H_ + h) * T_;
    const int P = spl[b];

    // load Q hi/lo: 128 rows x 8 uint4 each
    for (int i = tid; i < 2048; i += 256) {
        const int arr = i >> 10;            // 0=hi 1=lo
        const int r = (i >> 3) & 127;
        const int c8 = i & 7;
        const __nv_bfloat16* src = (arr == 0 ? g_Qh : g_Ql) + (bh + q0 + r) * D_ + c8 * 8;
        __nv_bfloat16* dst = (arr == 0 ? Qh : Ql) + r * ASP + c8 * 8;
        *(uint4*)dst = *(const uint4*)src;
    }

    // ldmatrix base addresses
    const int a_row = wid * 16 + (lane & 7) + ((lane >> 3) & 1) * 8;
    const int a_kg = (lane >> 4) * 8;
    const uint32_t qh_a = smem_u32(Qh + a_row * ASP + a_kg);
    const uint32_t ql_a = smem_u32(Ql + a_row * ASP + a_kg);
    const int k_row = (lane & 7) + (lane >> 4) * 8;
    const int k_col = ((lane >> 3) & 1) * 8;
    const uint32_t kh_a = smem_u32(Kh + k_row * ASP + k_col);
    const uint32_t kl_a = smem_u32(Kl + k_row * ASP + k_col);
    const int v_row = ((lane >> 3) & 1) * 8 + (lane & 7);
    const int v_col = (lane >> 4) * 8;
    const uint32_t vh_a = smem_u32(Vh + v_row * ASP + v_col);
    const uint32_t vl_a = smem_u32(Vl + v_row * ASP + v_col);

    float o[8][4];
    #pragma unroll
    for (int i = 0; i < 8; i++)
        #pragma unroll
        for (int j = 0; j < 4; j++) o[i][j] = 0.f;
    float lsum0 = 0.f, lsum1 = 0.f;
    const int row0 = q0 + wid * 16 + (lane >> 2);

    for (int kt = 0; kt < T_ / 64; kt++) {
        const int k0 = kt * 64;
        const bool tv = (k0 < P) || ((k0 <= q0 + 127) && (k0 + 63 >= q0 - WIN_));
        if (!tv) continue;   // uniform across block

        __syncthreads();
        // load K,V hi/lo tiles: 4 arrays x 64 rows x 8 uint4
        for (int i = tid; i < 2048; i += 256) {
            const int arr = i >> 9;
            const int r = (i >> 3) & 63;
            const int c8 = i & 7;
            const __nv_bfloat16* src =
                (arr == 0 ? g_Kh : arr == 1 ? g_Kl : arr == 2 ? g_Vh : g_Vl)
                + (bh + k0 + r) * D_ + c8 * 8;
            __nv_bfloat16* dst =
                (arr == 0 ? Kh : arr == 1 ? Kl : arr == 2 ? Vh : Vl) + r * ASP + c8 * 8;
            *(uint4*)dst = *(const uint4*)src;
        }
        __syncthreads();

        // ---- QK^T -> s[8][4] fp32 fragments ----
        float s[8][4];
        #pragma unroll
        for (int i = 0; i < 8; i++)
            #pragma unroll
            for (int j = 0; j < 4; j++) s[i][j] = 0.f;

        #pragma unroll
        for (int kk4 = 0; kk4 < 4; kk4++) {
            uint32_t qa_h[4], qa_l[4];
            LDMX4(qa_h[0], qa_h[1], qa_h[2], qa_h[3], qh_a + kk4 * 32);
            LDMX4(qa_l[0], qa_l[1], qa_l[2], qa_l[3], ql_a + kk4 * 32);
            #pragma unroll
            for (int nf2 = 0; nf2 < 4; nf2++) {
                uint32_t kb_h[4], kb_l[4];
                const uint32_t off = (uint32_t)(nf2 * 16 * ASP) * 2 + kk4 * 32;
                LDMX4(kb_h[0], kb_h[1], kb_h[2], kb_h[3], kh_a + off);
                LDMX4(kb_l[0], kb_l[1], kb_l[2], kb_l[3], kl_a + off);
                MMA16816(s[nf2*2], qa_h[0], qa_h[1], qa_h[2], qa_h[3], kb_h[0], kb_h[1]);
                MMA16816(s[nf2*2], qa_h[0], qa_h[1], qa_h[2], qa_h[3], kb_l[0], kb_l[1]);
                MMA16816(s[nf2*2], qa_l[0], qa_l[1], qa_l[2], qa_l[3], kb_h[0], kb_h[1]);
                MMA16816(s[nf2*2+1], qa_h[0], qa_h[1], qa_h[2], qa_h[3], kb_h[2], kb_h[3]);
                MMA16816(s[nf2*2+1], qa_h[0], qa_h[1], qa_h[2], qa_h[3], kb_l[2], kb_l[3]);
                MMA16816(s[nf2*2+1], qa_l[0], qa_l[1], qa_l[2], qa_l[3], kb_h[2], kb_h[3]);
            }
        }

        // ---- softcap/mask/exp + C->A repack + PV, per k16 group ----
        #pragma unroll
        for (int kc = 0; kc < 4; kc++) {
            uint32_t pah[4], pal[4];
            #pragma unroll
            for (int j = 0; j < 2; j++) {
                const int nf = kc * 2 + j;
                const int cb = k0 + nf * 8 + (lane & 3) * 2;
                const float p0 = softp(s[nf][0], row0,     cb,     P);
                const float p1 = softp(s[nf][1], row0,     cb + 1, P);
                const float p2 = softp(s[nf][2], row0 + 8, cb,     P);
                const float p3 = softp(s[nf][3], row0 + 8, cb + 1, P);
                lsum0 += p0 + p1;
                lsum1 += p2 + p3;
                uint32_t h01, h23;
                PACKBF2(h01, p0, p1);
                PACKBF2(h23, p2, p3);
                pah[j*2]   = h01;
                pah[j*2+1] = h23;
                const float r0 = p0 - __uint_as_float(h01 << 16);
                const float r1 = p1 - __uint_as_float(h01 & 0xFFFF0000u);
                const float r2 = p2 - __uint_as_float(h23 << 16);
                const float r3 = p3 - __uint_as_float(h23 & 0xFFFF0000u);
                uint32_t l01, l23;
                PACKBF2(l01, r0, r1);
                PACKBF2(l23, r2, r3);
                pal[j*2]   = l01;
                pal[j*2+1] = l23;
            }
            #pragma unroll
            for (int nf2 = 0; nf2 < 4; nf2++) {
                uint32_t vb_h[4], vb_l[4];
                const uint32_t off = (uint32_t)(kc * 16 * ASP + nf2 * 16) * 2;
                LDMX4T(vb_h[0], vb_h[1], vb_h[2], vb_h[3], vh_a + off);
                LDMX4T(vb_l[0], vb_l[1], vb_l[2], vb_l[3], vl_a + off);
                MMA16816(o[nf2*2], pah[0], pah[1], pah[2], pah[3], vb_h[0], vb_h[1]);
                MMA16816(o[nf2*2], pah[0], pah[1], pah[2], pah[3], vb_l[0], vb_l[1]);
                MMA16816(o[nf2*2], pal[0], pal[1], pal[2], pal[3], vb_h[0], vb_h[1]);
                MMA16816(o[nf2*2+1], pah[0], pah[1], pah[2], pah[3], vb_h[2], vb_h[3]);
                MMA16816(o[nf2*2+1], pah[0], pah[1], pah[2], pah[3], vb_l[2], vb_l[3]);
                MMA16816(o[nf2*2+1], pal[0], pal[1], pal[2], pal[3], vb_h[2], vb_h[3]);
            }
        }
    }

    // ---- normalize + write bf16 hi/lo ----
    lsum0 += __shfl_xor_sync(0xffffffffu, lsum0, 1);
    lsum0 += __shfl_xor_sync(0xffffffffu, lsum0, 2);
    lsum1 += __shfl_xor_sync(0xffffffffu, lsum1, 1);
    lsum1 += __shfl_xor_sync(0xffffffffu, lsum1, 2);
    const float inv0 = 1.0f / lsum0;
    const float inv1 = 1.0f / lsum1;

    const size_t base0 = ((size_t)(b * T_) + row0) * C_ + h * D_ + (lane & 3) * 2;
    const size_t base1 = base0 + (size_t)8 * C_;
    #pragma unroll
    for (int nf = 0; nf < 8; nf++) {
        const float y0 = o[nf][0] * inv0, y1 = o[nf][1] * inv0;
        const float y2 = o[nf][2] * inv1, y3 = o[nf][3] * inv1;
        uint32_t h01, h23;
        PACKBF2(h01, y0, y1);
        PACKBF2(h23, y2, y3);
        const float r0 = y0 - __uint_as_float(h01 << 16);
        const float r1 = y1 - __uint_as_float(h01 & 0xFFFF0000u);
        const float r2 = y2 - __uint_as_float(h23 << 16);
        const float r3 = y3 - __uint_as_float(h23 & 0xFFFF0000u);
        uint32_t l01, l23;
        PACKBF2(l01, r0, r1);
        PACKBF2(l23, r2, r3);
        *(uint32_t*)(g_ah + base0 + nf * 8) = h01;
        *(uint32_t*)(g_al + base0 + nf * 8) = l01;
        *(uint32_t*)(g_ah + base1 + nf * 8) = h23;
        *(uint32_t*)(g_al + base1 + nf * 8) = l23;
    }
}

// ---------------------------------------------------------------------------
extern "C" void kernel_launch(void* const* d_in, const int* in_sizes, int n_in,
                              void* d_out, int out_size)
{
    (void)in_sizes; (void)n_in; (void)out_size;
    const float* x    = (const float*)d_in[0];
    const int*   spl  = (const int*)  d_in[1];
    const float* Wqkv = (const float*)d_in[2];
    const float* bqkv = (const float*)d_in[3];
    const float* Wprj = (const float*)d_in[4];
    const float* bprj = (const float*)d_in[5];
    float* out = (float*)d_out;

    cudaFuncSetAttribute(attn_kernel,
                         cudaFuncAttributeMaxDynamicSharedMemorySize, ATTN_SMEM);
    cudaFuncSetAttribute(gemm_bf16_kernel<0>,
                         cudaFuncAttributeMaxDynamicSharedMemorySize, GSMEM);
    cudaFuncSetAttribute(gemm_bf16_kernel<1>,
                         cudaFuncAttributeMaxDynamicSharedMemorySize, GSMEM);

    __nv_bfloat16 *xh, *xl, *wqh, *wql, *wph, *wpl, *ah, *al;
    cudaGetSymbolAddress((void**)&xh,  g_xh);  cudaGetSymbolAddress((void**)&xl,  g_xl);
    cudaGetSymbolAddress((void**)&wqh, g_wqh); cudaGetSymbolAddress((void**)&wql, g_wql);
    cudaGetSymbolAddress((void**)&wph, g_wph); cudaGetSymbolAddress((void**)&wpl, g_wpl);
    cudaGetSymbolAddress((void**)&ah,  g_ah);  cudaGetSymbolAddress((void**)&al,  g_al);

    // 0) split fp32 inputs into bf16 hi/lo
    split_kernel<<<(B_*T_*C_/4 + 255)/256, 256>>>(x, xh, xl, B_*T_*C_/4);
    split_kernel<<<(3*C_*C_/4 + 255)/256, 256>>>(Wqkv, wqh, wql, 3*C_*C_/4);
    split_kernel<<<(C_*C_/4 + 255)/256, 256>>>(Wprj, wph, wpl, C_*C_/4);

    // 1) QKV projection (HMMA) -> g_{Q,K,V}{h,l}
    gemm_bf16_kernel<0><<<dim3(3*C_/128, B_*T_/128), 256, GSMEM>>>(
        xh, xl, wqh, wql, bqkv, nullptr);

    // 2) attention (HMMA) -> g_ah/g_al
    attn_kernel<<<dim3(T_/128, H_, B_), 256, ATTN_SMEM>>>(spl);

    // 3) output projection (HMMA) -> d_out
    gemm_bf16_kernel<1><<<dim3(C_/128, B_*T_/128), 256, GSMEM>>>(
        ah, al, wph, wpl, bprj, out);
}

// round 7
// speedup vs baseline: 1.0424x; 1.0424x over previous
#include <cuda_runtime.h>
#include <cuda_bf16.h>
#include <math.h>
#include <stdint.h>

// Problem constants
#define B_ 2
#define T_ 2048
#define C_ 1024
#define H_ 16
#define D_ 64
#define WIN_ 512
#define K_ 1024

// GEMM tiling: BK=16 per stage, 4-stage cp.async pipeline
#define BK 16
#define SP 24                       // padded smem row stride (bf16 elems)
#define TILE_B (128 * SP * 2)       // 6144 B per 128xBK tile
#define STAGE_B (4 * TILE_B)        // Ah, Al, Bh, Bl = 24576 B
#define NSTAGE 4
#define GSMEM (NSTAGE * STAGE_B)    // 98304 B

// Attention smem
#define ASP 72                      // padded row stride (bf16 elems)
#define ATTN_SMEM ((2*128 + 4*64) * ASP * 2)   // 73728 bytes

// ---------------- scratch (allocation-free) ----------------
__device__ __nv_bfloat16 g_Qh[B_*H_*T_*D_], g_Ql[B_*H_*T_*D_];
__device__ __nv_bfloat16 g_Kh[B_*H_*T_*D_], g_Kl[B_*H_*T_*D_];
__device__ __nv_bfloat16 g_Vh[B_*H_*T_*D_], g_Vl[B_*H_*T_*D_];
__device__ __nv_bfloat16 g_xh[B_*T_*C_],  g_xl[B_*T_*C_];
__device__ __nv_bfloat16 g_wqh[3*C_*C_],  g_wql[3*C_*C_];
__device__ __nv_bfloat16 g_wph[C_*C_],    g_wpl[C_*C_];
__device__ __nv_bfloat16 g_ah[B_*T_*C_],  g_al[B_*T_*C_];

__device__ __forceinline__ uint32_t smem_u32(const void* p) {
    uint32_t a;
    asm("{ .reg .u64 t; cvta.to.shared.u64 t, %1; cvt.u32.u64 %0, t; }"
        : "=r"(a) : "l"(p));
    return a;
}
#define LDMX4(r0, r1, r2, r3, addr)                                          \
    asm volatile("ldmatrix.sync.aligned.m8n8.x4.shared.b16 {%0,%1,%2,%3}, [%4];" \
        : "=r"(r0), "=r"(r1), "=r"(r2), "=r"(r3) : "r"(addr))
#define LDMX4T(r0, r1, r2, r3, addr)                                         \
    asm volatile("ldmatrix.sync.aligned.m8n8.x4.trans.shared.b16 {%0,%1,%2,%3}, [%4];" \
        : "=r"(r0), "=r"(r1), "=r"(r2), "=r"(r3) : "r"(addr))
#define MMA16816(c, a0, a1, a2, a3, b0, b1)                                  \
    asm volatile("mma.sync.aligned.m16n8k16.row.col.f32.bf16.bf16.f32 "      \
        "{%0,%1,%2,%3}, {%4,%5,%6,%7}, {%8,%9}, {%0,%1,%2,%3};"              \
        : "+f"((c)[0]), "+f"((c)[1]), "+f"((c)[2]), "+f"((c)[3])             \
        : "r"(a0), "r"(a1), "r"(a2), "r"(a3), "r"(b0), "r"(b1))
#define PACKBF2(r, lo, hi)                                                   \
    asm("cvt.rn.bf16x2.f32 %0, %1, %2;" : "=r"(r) : "f"(hi), "f"(lo))
#define CP16(dst, src)                                                       \
    asm volatile("cp.async.cg.shared.global [%0], [%1], 16;" :: "r"(dst), "l"(src))
#define CP_COMMIT() asm volatile("cp.async.commit_group;" ::: "memory")
#define CP_WAIT(n)  asm volatile("cp.async.wait_group %0;" :: "n"(n) : "memory")

// ---------------- split fp32 -> bf16 hi/lo ----------------
__global__ __launch_bounds__(256) void split_kernel(
    const float* __restrict__ s, __nv_bfloat16* __restrict__ hi,
    __nv_bfloat16* __restrict__ lo, int n4)
{
    int i = blockIdx.x * 256 + threadIdx.x;
    if (i >= n4) return;
    float4 v = ((const float4*)s)[i];
    __nv_bfloat16 h0 = __float2bfloat16(v.x), h1 = __float2bfloat16(v.y);
    __nv_bfloat16 h2 = __float2bfloat16(v.z), h3 = __float2bfloat16(v.w);
    __nv_bfloat16 l0 = __float2bfloat16(v.x - __bfloat162float(h0));
    __nv_bfloat16 l1 = __float2bfloat16(v.y - __bfloat162float(h1));
    __nv_bfloat16 l2 = __float2bfloat16(v.z - __bfloat162float(h2));
    __nv_bfloat16 l3 = __float2bfloat16(v.w - __bfloat162float(h3));
    ((__nv_bfloat162*)hi)[2*i]   = __nv_bfloat162(h0, h1);
    ((__nv_bfloat162*)hi)[2*i+1] = __nv_bfloat162(h2, h3);
    ((__nv_bfloat162*)lo)[2*i]   = __nv_bfloat162(l0, l1);
    ((__nv_bfloat162*)lo)[2*i+1] = __nv_bfloat162(l2, l3);
}

// ---------------- bf16-split tensor-core GEMM (HMMA, 4-stage cp.async) ----
// D[m,n] = sum_k A[m,k]*W[n,k] + bias[n] ~= Ah*Wh + Ah*Wl + Al*Wh.
// CTA 128x128, BK=16, 256 threads = 8 warps (4m x 2n), warp tile 32x64.
// ONE __syncthreads per K16 step; direct-from-fragment epilogue (no staging).
// MODE 0: split-scatter into g_{Q,K,V}{h,l}.  MODE 1: fp32 row-major out.
template <int MODE>
__global__ __launch_bounds__(256, 2) void gemm_bf16_kernel(
    const __nv_bfloat16* __restrict__ Ahi, const __nv_bfloat16* __restrict__ Alo,
    const __nv_bfloat16* __restrict__ Bhi, const __nv_bfloat16* __restrict__ Blo,
    const float* __restrict__ bias, float* __restrict__ Cout)
{
    extern __shared__ char smem[];
    const uint32_t sb = smem_u32(smem);
    const int tid = threadIdx.x;
    const int wid = tid >> 5;
    const int lane = tid & 31;
    const int warp_m = wid & 3;      // 0..3, 32 rows each
    const int warp_n = wid >> 2;     // 0..1, 64 cols each
    const int bn = blockIdx.x, bm = blockIdx.y;

    // cp.async mapping: thread -> row (tid>>1), 8-elem 16B chunk ((tid&1)*8)
    const int grow = tid >> 1;
    const int gc8  = (tid & 1) * 8;
    const __nv_bfloat16* srcs[4] = {
        Ahi + (size_t)(bm * 128 + grow) * K_ + gc8,
        Alo + (size_t)(bm * 128 + grow) * K_ + gc8,
        Bhi + (size_t)(bn * 128 + grow) * K_ + gc8,
        Blo + (size_t)(bn * 128 + grow) * K_ + gc8 };
    const uint32_t soff = (uint32_t)(grow * SP + gc8) * 2;

    // ldmatrix per-lane offsets (bytes within a tile)
    const uint32_t aoff = (uint32_t)(
        (warp_m * 32 + (lane & 7) + ((lane >> 3) & 1) * 8) * SP
        + (lane >> 4) * 8) * 2;
    const uint32_t boff = (uint32_t)(
        (warp_n * 64 + (lane & 7) + (lane >> 4) * 8) * SP
        + ((lane >> 3) & 1) * 8) * 2;

    float acc[2][8][4];
    #pragma unroll
    for (int i = 0; i < 2; i++)
        #pragma unroll
        for (int j = 0; j < 8; j++)
            #pragma unroll
            for (int c = 0; c < 4; c++) acc[i][j][c] = 0.f;

    const int NT = K_ / BK;   // 64

    // prologue: fill stages 0..2
    #pragma unroll
    for (int st = 0; st < NSTAGE - 1; st++) {
        const uint32_t db = sb + st * STAGE_B;
        #pragma unroll
        for (int t = 0; t < 4; t++)
            CP16(db + t * TILE_B + soff, srcs[t] + st * BK);
        CP_COMMIT();
    }

    for (int it = 0; it < NT; ++it) {
        CP_WAIT(NSTAGE - 2);          // stage `it` complete
        __syncthreads();              // visible to all warps
        const uint32_t tb = sb + (uint32_t)(it & (NSTAGE - 1)) * STAGE_B;

        // prefetch stage it+3 (buffer not read this iter or last iter)
        if (it + NSTAGE - 1 < NT) {
            const uint32_t db = sb + (uint32_t)((it + NSTAGE - 1) & (NSTAGE - 1)) * STAGE_B;
            #pragma unroll
            for (int t = 0; t < 4; t++)
                CP16(db + t * TILE_B + soff, srcs[t] + (it + NSTAGE - 1) * BK);
        }
        CP_COMMIT();                  // uniform group arithmetic

        // compute this K16 slab
        uint32_t ah[2][4], al[2][4];
        #pragma unroll
        for (int mf = 0; mf < 2; mf++) {
            const uint32_t ao = tb + aoff + (uint32_t)(mf * 16 * SP) * 2;
            LDMX4(ah[mf][0], ah[mf][1], ah[mf][2], ah[mf][3], ao);
            LDMX4(al[mf][0], al[mf][1], al[mf][2], al[mf][3], ao + TILE_B);
        }
        #pragma unroll
        for (int nf2 = 0; nf2 < 4; nf2++) {
            uint32_t bh[4], bl[4];
            const uint32_t bo = tb + 2 * TILE_B + boff + (uint32_t)(nf2 * 16 * SP) * 2;
            LDMX4(bh[0], bh[1], bh[2], bh[3], bo);
            LDMX4(bl[0], bl[1], bl[2], bl[3], bo + TILE_B);
            #pragma unroll
            for (int mf = 0; mf < 2; mf++) {
                MMA16816(acc[mf][nf2*2], ah[mf][0], ah[mf][1], ah[mf][2], ah[mf][3],
                         bh[0], bh[1]);
                MMA16816(acc[mf][nf2*2], ah[mf][0], ah[mf][1], ah[mf][2], ah[mf][3],
                         bl[0], bl[1]);
                MMA16816(acc[mf][nf2*2], al[mf][0], al[mf][1], al[mf][2], al[mf][3],
                         bh[0], bh[1]);
                MMA16816(acc[mf][nf2*2+1], ah[mf][0], ah[mf][1], ah[mf][2], ah[mf][3],
                         bh[2], bh[3]);
                MMA16816(acc[mf][nf2*2+1], ah[mf][0], ah[mf][1], ah[mf][2], ah[mf][3],
                         bl[2], bl[3]);
                MMA16816(acc[mf][nf2*2+1], al[mf][0], al[mf][1], al[mf][2], al[mf][3],
                         bh[2], bh[3]);
            }
        }
    }
    CP_WAIT(0);   // drain any trailing (empty) groups before exit

    // ---- direct-from-fragment epilogue ----
    const int g = lane >> 2, tg = lane & 3;
    #pragma unroll
    for (int mf = 0; mf < 2; mf++) {
        #pragma unroll
        for (int nf = 0; nf < 8; nf++) {
            const int c0 = warp_n * 64 + nf * 8 + tg * 2;     // block-local col
            const float b0 = bias[bn * 128 + c0];
            const float b1 = bias[bn * 128 + c0 + 1];
            const int r0 = warp_m * 32 + mf * 16 + g;
            const float v0 = acc[mf][nf][0] + b0, v1 = acc[mf][nf][1] + b1;
            const float v2 = acc[mf][nf][2] + b0, v3 = acc[mf][nf][3] + b1;
            if (MODE == 0) {
                const int sel = bn >> 3;
                const int h = ((bn & 7) << 1) + (c0 >> 6);
                const int dd = c0 & 63;
                __nv_bfloat16 *dh, *dl;
                if (sel == 0)      { dh = g_Qh; dl = g_Ql; }
                else if (sel == 1) { dh = g_Kh; dl = g_Kl; }
                else               { dh = g_Vh; dl = g_Vl; }
                #pragma unroll
                for (int rr = 0; rr < 2; rr++) {
                    const int m = bm * 128 + r0 + rr * 8;
                    const int b = m >> 11, t = m & 2047;
                    const float y0 = rr ? v2 : v0, y1 = rr ? v3 : v1;
                    uint32_t hp, lp;
                    PACKBF2(hp, y0, y1);
                    const float e0 = y0 - __uint_as_float(hp << 16);
                    const float e1 = y1 - __uint_as_float(hp & 0xFFFF0000u);
                    PACKBF2(lp, e0, e1);
                    const size_t o = (((size_t)(b * H_ + h)) * T_ + t) * D_ + dd;
                    *(uint32_t*)(dh + o) = hp;
                    *(uint32_t*)(dl + o) = lp;
                }
            } else {
                #pragma unroll
                for (int rr = 0; rr < 2; rr++) {
                    const int m = bm * 128 + r0 + rr * 8;
                    float2 y;
                    y.x = rr ? v2 : v0;
                    y.y = rr ? v3 : v1;
                    *(float2*)(Cout + (size_t)m * C_ + bn * 128 + c0) = y;
                }
            }
        }
    }
}

// softcap+mask+exp with fixed max 30: p = exp(-60/(E+1)), E = exp(s/15)
__device__ __forceinline__ float softp(float raw, int qr, int kg, int P) {
    const float sc = raw * 0.125f;
    const float E = __expf(sc * (1.0f / 15.0f));
    const float p = __expf(__fdividef(-60.0f, E + 1.0f));
    const bool valid = ((kg <= qr) && (qr - kg <= WIN_)) || (kg < P);
    return valid ? p : 0.0f;
}

// ---------------------------------------------------------------------------
// HMMA attention: 128 q-rows/CTA, 8 warps (16 q-rows each), 64-key tiles.
// QK^T: Qh*Kh + Qh*Kl + Ql*Kh.  PV: Ph*Vh + Ph*Vl + Pl*Vh.
// P repacked C->A fragments in registers (no smem round trip).
// ---------------------------------------------------------------------------
__global__ __launch_bounds__(256, 2) void attn_kernel(const int* __restrict__ spl)
{
    extern __shared__ __nv_bfloat16 asmem[];
    __nv_bfloat16* Qh = asmem;               // [128][ASP]
    __nv_bfloat16* Ql = Qh + 128 * ASP;
    __nv_bfloat16* Kh = Ql + 128 * ASP;      // [64][ASP]
    __nv_bfloat16* Kl = Kh + 64 * ASP;
    __nv_bfloat16* Vh = Kl + 64 * ASP;       // [64][ASP]
    __nv_bfloat16* Vl = Vh + 64 * ASP;

    const int tid = threadIdx.x;
    const int wid = tid >> 5;      // 0..7
    const int lane = tid & 31;
    const int q0 = blockIdx.x * 128;
    const int h = blockIdx.y;
    const int b = blockIdx.z;
    const size_t bh = (size_t)(b * H_ + h) * T_;
    const int P = spl[b];

    // load Q hi/lo: 128 rows x 8 uint4 each
    for (int i = tid; i < 2048; i += 256) {
        const int arr = i >> 10;            // 0=hi 1=lo
        const int r = (i >> 3) & 127;
        const int c8 = i & 7;
        const __nv_bfloat16* src = (arr == 0 ? g_Qh : g_Ql) + (bh + q0 + r) * D_ + c8 * 8;
        __nv_bfloat16* dst = (arr == 0 ? Qh : Ql) + r * ASP + c8 * 8;
        *(uint4*)dst = *(const uint4*)src;
    }

    // ldmatrix base addresses
    const int a_row = wid * 16 + (lane & 7) + ((lane >> 3) & 1) * 8;
    const int a_kg = (lane >> 4) * 8;
    const uint32_t qh_a = smem_u32(Qh + a_row * ASP + a_kg);
    const uint32_t ql_a = smem_u32(Ql + a_row * ASP + a_kg);
    const int k_row = (lane & 7) + (lane >> 4) * 8;
    const int k_col = ((lane >> 3) & 1) * 8;
    const uint32_t kh_a = smem_u32(Kh + k_row * ASP + k_col);
    const uint32_t kl_a = smem_u32(Kl + k_row * ASP + k_col);
    const int v_row = ((lane >> 3) & 1) * 8 + (lane & 7);
    const int v_col = (lane >> 4) * 8;
    const uint32_t vh_a = smem_u32(Vh + v_row * ASP + v_col);
    const uint32_t vl_a = smem_u32(Vl + v_row * ASP + v_col);

    float o[8][4];
    #pragma unroll
    for (int i = 0; i < 8; i++)
        #pragma unroll
        for (int j = 0; j < 4; j++) o[i][j] = 0.f;
    float lsum0 = 0.f, lsum1 = 0.f;
    const int row0 = q0 + wid * 16 + (lane >> 2);

    for (int kt = 0; kt < T_ / 64; kt++) {
        const int k0 = kt * 64;
        const bool tv = (k0 < P) || ((k0 <= q0 + 127) && (k0 + 63 >= q0 - WIN_));
        if (!tv) continue;   // uniform across block

        __syncthreads();
        // load K,V hi/lo tiles: 4 arrays x 64 rows x 8 uint4
        for (int i = tid; i < 2048; i += 256) {
            const int arr = i >> 9;
            const int r = (i >> 3) & 63;
            const int c8 = i & 7;
            const __nv_bfloat16* src =
                (arr == 0 ? g_Kh : arr == 1 ? g_Kl : arr == 2 ? g_Vh : g_Vl)
                + (bh + k0 + r) * D_ + c8 * 8;
            __nv_bfloat16* dst =
                (arr == 0 ? Kh : arr == 1 ? Kl : arr == 2 ? Vh : Vl) + r * ASP + c8 * 8;
            *(uint4*)dst = *(const uint4*)src;
        }
        __syncthreads();

        // ---- QK^T -> s[8][4] fp32 fragments ----
        float s[8][4];
        #pragma unroll
        for (int i = 0; i < 8; i++)
            #pragma unroll
            for (int j = 0; j < 4; j++) s[i][j] = 0.f;

        #pragma unroll
        for (int kk4 = 0; kk4 < 4; kk4++) {
            uint32_t qa_h[4], qa_l[4];
            LDMX4(qa_h[0], qa_h[1], qa_h[2], qa_h[3], qh_a + kk4 * 32);
            LDMX4(qa_l[0], qa_l[1], qa_l[2], qa_l[3], ql_a + kk4 * 32);
            #pragma unroll
            for (int nf2 = 0; nf2 < 4; nf2++) {
                uint32_t kb_h[4], kb_l[4];
                const uint32_t off = (uint32_t)(nf2 * 16 * ASP) * 2 + kk4 * 32;
                LDMX4(kb_h[0], kb_h[1], kb_h[2], kb_h[3], kh_a + off);
                LDMX4(kb_l[0], kb_l[1], kb_l[2], kb_l[3], kl_a + off);
                MMA16816(s[nf2*2], qa_h[0], qa_h[1], qa_h[2], qa_h[3], kb_h[0], kb_h[1]);
                MMA16816(s[nf2*2], qa_h[0], qa_h[1], qa_h[2], qa_h[3], kb_l[0], kb_l[1]);
                MMA16816(s[nf2*2], qa_l[0], qa_l[1], qa_l[2], qa_l[3], kb_h[0], kb_h[1]);
                MMA16816(s[nf2*2+1], qa_h[0], qa_h[1], qa_h[2], qa_h[3], kb_h[2], kb_h[3]);
                MMA16816(s[nf2*2+1], qa_h[0], qa_h[1], qa_h[2], qa_h[3], kb_l[2], kb_l[3]);
                MMA16816(s[nf2*2+1], qa_l[0], qa_l[1], qa_l[2], qa_l[3], kb_h[2], kb_h[3]);
            }
        }

        // ---- softcap/mask/exp + C->A repack + PV, per k16 group ----
        #pragma unroll
        for (int kc = 0; kc < 4; kc++) {
            uint32_t pah[4], pal[4];
            #pragma unroll
            for (int j = 0; j < 2; j++) {
                const int nf = kc * 2 + j;
                const int cb = k0 + nf * 8 + (lane & 3) * 2;
                const float p0 = softp(s[nf][0], row0,     cb,     P);
                const float p1 = softp(s[nf][1], row0,     cb + 1, P);
                const float p2 = softp(s[nf][2], row0 + 8, cb,     P);
                const float p3 = softp(s[nf][3], row0 + 8, cb + 1, P);
                lsum0 += p0 + p1;
                lsum1 += p2 + p3;
                uint32_t h01, h23;
                PACKBF2(h01, p0, p1);
                PACKBF2(h23, p2, p3);
                pah[j*2]   = h01;
                pah[j*2+1] = h23;
                const float r0 = p0 - __uint_as_float(h01 << 16);
                const float r1 = p1 - __uint_as_float(h01 & 0xFFFF0000u);
                const float r2 = p2 - __uint_as_float(h23 << 16);
                const float r3 = p3 - __uint_as_float(h23 & 0xFFFF0000u);
                uint32_t l01, l23;
                PACKBF2(l01, r0, r1);
                PACKBF2(l23, r2, r3);
                pal[j*2]   = l01;
                pal[j*2+1] = l23;
            }
            #pragma unroll
            for (int nf2 = 0; nf2 < 4; nf2++) {
                uint32_t vb_h[4], vb_l[4];
                const uint32_t off = (uint32_t)(kc * 16 * ASP + nf2 * 16) * 2;
                LDMX4T(vb_h[0], vb_h[1], vb_h[2], vb_h[3], vh_a + off);
                LDMX4T(vb_l[0], vb_l[1], vb_l[2], vb_l[3], vl_a + off);
                MMA16816(o[nf2*2], pah[0], pah[1], pah[2], pah[3], vb_h[0], vb_h[1]);
                MMA16816(o[nf2*2], pah[0], pah[1], pah[2], pah[3], vb_l[0], vb_l[1]);
                MMA16816(o[nf2*2], pal[0], pal[1], pal[2], pal[3], vb_h[0], vb_h[1]);
                MMA16816(o[nf2*2+1], pah[0], pah[1], pah[2], pah[3], vb_h[2], vb_h[3]);
                MMA16816(o[nf2*2+1], pah[0], pah[1], pah[2], pah[3], vb_l[2], vb_l[3]);
                MMA16816(o[nf2*2+1], pal[0], pal[1], pal[2], pal[3], vb_h[2], vb_h[3]);
            }
        }
    }

    // ---- normalize + write bf16 hi/lo ----
    lsum0 += __shfl_xor_sync(0xffffffffu, lsum0, 1);
    lsum0 += __shfl_xor_sync(0xffffffffu, lsum0, 2);
    lsum1 += __shfl_xor_sync(0xffffffffu, lsum1, 1);
    lsum1 += __shfl_xor_sync(0xffffffffu, lsum1, 2);
    const float inv0 = 1.0f / lsum0;
    const float inv1 = 1.0f / lsum1;

    const size_t base0 = ((size_t)(b * T_) + row0) * C_ + h * D_ + (lane & 3) * 2;
    const size_t base1 = base0 + (size_t)8 * C_;
    #pragma unroll
    for (int nf = 0; nf < 8; nf++) {
        const float y0 = o[nf][0] * inv0, y1 = o[nf][1] * inv0;
        const float y2 = o[nf][2] * inv1, y3 = o[nf][3] * inv1;
        uint32_t h01, h23;
        PACKBF2(h01, y0, y1);
        PACKBF2(h23, y2, y3);
        const float r0 = y0 - __uint_as_float(h01 << 16);
        const float r1 = y1 - __uint_as_float(h01 & 0xFFFF0000u);
        const float r2 = y2 - __uint_as_float(h23 << 16);
        const float r3 = y3 - __uint_as_float(h23 & 0xFFFF0000u);
        uint32_t l01, l23;
        PACKBF2(l01, r0, r1);
        PACKBF2(l23, r2, r3);
        *(uint32_t*)(g_ah + base0 + nf * 8) = h01;
        *(uint32_t*)(g_al + base0 + nf * 8) = l01;
        *(uint32_t*)(g_ah + base1 + nf * 8) = h23;
        *(uint32_t*)(g_al + base1 + nf * 8) = l23;
    }
}

// ---------------------------------------------------------------------------
extern "C" void kernel_launch(void* const* d_in, const int* in_sizes, int n_in,
                              void* d_out, int out_size)
{
    (void)in_sizes; (void)n_in; (void)out_size;
    const float* x    = (const float*)d_in[0];
    const int*   spl  = (const int*)  d_in[1];
    const float* Wqkv = (const float*)d_in[2];
    const float* bqkv = (const float*)d_in[3];
    const float* Wprj = (const float*)d_in[4];
    const float* bprj = (const float*)d_in[5];
    float* out = (float*)d_out;

    cudaFuncSetAttribute(attn_kernel,
                         cudaFuncAttributeMaxDynamicSharedMemorySize, ATTN_SMEM);
    cudaFuncSetAttribute(gemm_bf16_kernel<0>,
                         cudaFuncAttributeMaxDynamicSharedMemorySize, GSMEM);
    cudaFuncSetAttribute(gemm_bf16_kernel<1>,
                         cudaFuncAttributeMaxDynamicSharedMemorySize, GSMEM);

    __nv_bfloat16 *xh, *xl, *wqh, *wql, *wph, *wpl, *ah, *al;
    cudaGetSymbolAddress((void**)&xh,  g_xh);  cudaGetSymbolAddress((void**)&xl,  g_xl);
    cudaGetSymbolAddress((void**)&wqh, g_wqh); cudaGetSymbolAddress((void**)&wql, g_wql);
    cudaGetSymbolAddress((void**)&wph, g_wph); cudaGetSymbolAddress((void**)&wpl, g_wpl);
    cudaGetSymbolAddress((void**)&ah,  g_ah);  cudaGetSymbolAddress((void**)&al,  g_al);

    // 0) split fp32 inputs into bf16 hi/lo
    split_kernel<<<(B_*T_*C_/4 + 255)/256, 256>>>(x, xh, xl, B_*T_*C_/4);
    split_kernel<<<(3*C_*C_/4 + 255)/256, 256>>>(Wqkv, wqh, wql, 3*C_*C_/4);
    split_kernel<<<(C_*C_/4 + 255)/256, 256>>>(Wprj, wph, wpl, C_*C_/4);

    // 1) QKV projection (HMMA) -> g_{Q,K,V}{h,l}
    gemm_bf16_kernel<0><<<dim3(3*C_/128, B_*T_/128), 256, GSMEM>>>(
        xh, xl, wqh, wql, bqkv, nullptr);

    // 2) attention (HMMA) -> g_ah/g_al
    attn_kernel<<<dim3(T_/128, H_, B_), 256, ATTN_SMEM>>>(spl);

    // 3) output projection (HMMA) -> d_out
    gemm_bf16_kernel<1><<<dim3(C_/128, B_*T_/128), 256, GSMEM>>>(
        ah, al, wph, wpl, bprj, out);
}